// round 11
// baseline (speedup 1.0000x reference)
#include <cuda_runtime.h>
#include <cuda_bf16.h>
#include <cstdint>
#include <cfloat>

// ---------------------------------------------------------------------------
// Loss_46102178955400 — bf16 mma.sync, triangular schedule, 1 group/CTA for
// occupancy (3 CTAs/SM). Smem tile X[buf][80][72] bf16 (rows 0-63 members,
// 64 centroid, 65-79 zero). 14 of 20 16x16 tiles computed across 8 warps.
// ---------------------------------------------------------------------------

#define LAMBDA_1 1.0f
#define LAMBDA_2 0.5f
#define KC     64          // f32 k-chunk per tile (-> 64 bf16 cols)
#define RG     80
#define PIT    72          // bf16 row pitch (144 B)
#define PITB   144
#define STRB   (16*PITB)   // bytes per 16-row strip
#define BUFE   (RG*PIT)    // bf16 elems per buffer (1 group)
#define BUFB   (BUFE*2)
#define MAXB   4096

__device__ double g_part[MAXB];
__device__ int    g_cnt = 0;

struct __align__(16) GS {
    __nv_bfloat16 X[2][RG][PIT];      // 23040 B
    const float*  rowp[65];           // 64 members + centroid
    float  sq_sh[64];
    float  csq;
    float  red[8];
    double dred[8];
    int    done;
};

__device__ __forceinline__ uint32_t smem_u32(const void* p) {
    uint32_t a;
    asm("{ .reg .u64 t; cvta.to.shared.u64 t, %1; cvt.u32.u64 %0, t; }"
        : "=r"(a) : "l"(p));
    return a;
}
__device__ __forceinline__ void ldm_x4(uint32_t a[4], uint32_t addr) {
    asm volatile("ldmatrix.sync.aligned.m8n8.x4.shared.b16 {%0,%1,%2,%3},[%4];"
                 : "=r"(a[0]), "=r"(a[1]), "=r"(a[2]), "=r"(a[3]) : "r"(addr));
}
__device__ __forceinline__ void mma_bf16(float* c, const uint32_t a[4],
                                         uint32_t b0, uint32_t b1) {
    asm volatile("mma.sync.aligned.m16n8k16.row.col.f32.bf16.bf16.f32 "
                 "{%0,%1,%2,%3},{%4,%5,%6,%7},{%8,%9},{%0,%1,%2,%3};"
                 : "+f"(c[0]), "+f"(c[1]), "+f"(c[2]), "+f"(c[3])
                 : "r"(a[0]), "r"(a[1]), "r"(a[2]), "r"(a[3]), "r"(b0), "r"(b1));
}
__device__ __forceinline__ void mma2(float* c8, const uint32_t A[4],
                                     const uint32_t B[4]) {
    mma_bf16(c8,     A, B[0], B[2]);
    mma_bf16(c8 + 4, A, B[1], B[3]);
}

template<int I, int J>
__device__ __forceinline__ void tile_dist(const float* a8, const float* sq,
                                          float csq, float& rsum, float& asum,
                                          int R0, int Cb) {
    #pragma unroll
    for (int h = 0; h < 2; h++)
        #pragma unroll
        for (int q = 0; q < 4; q++) {
            int r = 16 * I + R0 + ((q >> 1) << 3);
            int c = 16 * J + h * 8 + Cb + (q & 1);
            float v = a8[h * 4 + q];
            if (J < 4) {
                if (c > r) {
                    float d2 = sq[r] + sq[c] - 2.f * v;
                    rsum += (d2 > 0.f) ? sqrtf(d2) : 0.f;
                }
            } else if (c == 64) {
                float d2 = sq[r] + csq - 2.f * v;
                asum += (d2 > 0.f) ? sqrtf(d2) : 0.f;
            }
        }
}

__global__ __launch_bounds__(256, 3)
void fused_kernel(const float* __restrict__ train,
                  const int* __restrict__ tgt,
                  const float* __restrict__ unl,
                  const int* __restrict__ cids,
                  const int* __restrict__ mids,
                  float* __restrict__ out,
                  int C, int G, int n_train,
                  float inv_align, float inv_rob) {
    __shared__ GS s;
    const int tid  = threadIdx.x;
    const int wid  = tid >> 5;
    const int lane = tid & 31;

    double blk_part = 0.0;   // valid on tid 0 only

    if ((int)blockIdx.x >= G) {
        // ======================= CE path ==================================
        int row = ((int)blockIdx.x - G) * 8 + wid;
        float nll = 0.f;
        if (row < n_train) {
            const float* x  = train + (size_t)row * C;
            const float4* x4 = (const float4*)x;
            const int nv = C >> 2;
            float4 v[8];
            bool   pv[8];
            #pragma unroll
            for (int q = 0; q < 8; q++) {
                int i = lane + q * 32;
                pv[q] = (i < nv);
                v[q]  = pv[q] ? x4[i] : make_float4(-FLT_MAX, -FLT_MAX,
                                                    -FLT_MAX, -FLT_MAX);
            }
            float mx = -FLT_MAX;
            #pragma unroll
            for (int q = 0; q < 8; q++)
                mx = fmaxf(mx, fmaxf(fmaxf(v[q].x, v[q].y),
                                     fmaxf(v[q].z, v[q].w)));
            for (int c = (nv << 2) + lane; c < C; c += 32) mx = fmaxf(mx, x[c]);
            #pragma unroll
            for (int o = 16; o; o >>= 1)
                mx = fmaxf(mx, __shfl_xor_sync(~0u, mx, o));
            float sm = 0.f;
            #pragma unroll
            for (int q = 0; q < 8; q++) {
                if (pv[q])
                    sm += __expf(v[q].x - mx) + __expf(v[q].y - mx) +
                          __expf(v[q].z - mx) + __expf(v[q].w - mx);
            }
            for (int c = (nv << 2) + lane; c < C; c += 32) sm += __expf(x[c] - mx);
            #pragma unroll
            for (int o = 16; o; o >>= 1) sm += __shfl_xor_sync(~0u, sm, o);
            nll = -(x[tgt[row]] - mx - logf(sm));
        }
        if (lane == 0) s.red[wid] = nll;
        __syncthreads();
        if (tid == 0) {
            double acc = 0.0;
            #pragma unroll
            for (int i = 0; i < 8; i++) acc += (double)s.red[i];
            blk_part = acc / (double)n_train;
        }
    } else {
        // ======================= group path ===============================
        const int g = (int)blockIdx.x;

        if (tid < 64)       s.rowp[tid] = unl + (size_t)mids[g * 64 + tid] * C;
        else if (tid == 64) s.rowp[64]  = train + (size_t)cids[g] * C;

        {   // zero pad rows 65..79 in both buffers
            uint32_t* pz = (uint32_t*)&s.X[0][0][0];
            for (int i = tid; i < 2 * 15 * (PIT / 2); i += 256) {
                int b   = i / (15 * (PIT / 2));
                int rem = i - b * 15 * (PIT / 2);
                int r   = 65 + rem / (PIT / 2);
                int c   = rem % (PIT / 2);
                pz[(b * RG + r) * (PIT / 2) + c] = 0u;
            }
        }
        __syncthreads();

        // ---- coalesced load: warp w owns member rows [8w, 8w+8) ----------
        const int sub = lane >> 4;
        const int cc  = (lane & 15) << 2;
        const int fl0 = (wid << 3) + sub;
        __nv_bfloat16* pdst0 = &s.X[0][fl0][cc];
        const bool is_c = (wid == 0) && (lane < 16);
        __nv_bfloat16* pcd = &s.X[0][64][cc];
        float csq_loc = 0.f;

        const uint32_t xbase = smem_u32(&s.X[0][0][0]);
        const int q8 = lane >> 3;
        const uint32_t lmo = (uint32_t)(((lane & 7) + ((q8 & 1) << 3)) * PITB +
                                        (((q8 >> 1) << 3) << 1));

        float acc[2][8];
        #pragma unroll
        for (int i = 0; i < 2; i++)
            #pragma unroll
            for (int j = 0; j < 8; j++) acc[i][j] = 0.f;

        const int ntiles = (C + KC - 1) / KC;
        float4 vr[4], vc = make_float4(0.f, 0.f, 0.f, 0.f);

        auto load_tile = [&](int t) {
            const int c0 = t * KC, cols = C - c0;
            if (cols >= KC) {
                #pragma unroll
                for (int j = 0; j < 4; j++)
                    vr[j] = *(const float4*)(s.rowp[fl0 + 2 * j] + c0 + cc);
                if (is_c) vc = *(const float4*)(s.rowp[64] + c0 + cc);
            } else {
                const bool full = (cc + 4 <= cols);
                #pragma unroll
                for (int j = 0; j < 4; j++) {
                    const float* p = s.rowp[fl0 + 2 * j] + c0 + cc;
                    float4 v = make_float4(0.f, 0.f, 0.f, 0.f);
                    if (full) v = *(const float4*)p;
                    else {
                        if (cc + 0 < cols) v.x = p[0];
                        if (cc + 1 < cols) v.y = p[1];
                        if (cc + 2 < cols) v.z = p[2];
                    }
                    vr[j] = v;
                }
                if (is_c) {
                    const float* p = s.rowp[64] + c0 + cc;
                    float4 v = make_float4(0.f, 0.f, 0.f, 0.f);
                    if (full) v = *(const float4*)p;
                    else {
                        if (cc + 0 < cols) v.x = p[0];
                        if (cc + 1 < cols) v.y = p[1];
                        if (cc + 2 < cols) v.z = p[2];
                    }
                    vc = v;
                }
            }
        };
        auto store_tile = [&](int b) {
            __nv_bfloat16* d = pdst0 + b * BUFE;
            #pragma unroll
            for (int j = 0; j < 4; j++) {
                __nv_bfloat162 h0 = __float22bfloat162_rn(make_float2(vr[j].x, vr[j].y));
                __nv_bfloat162 h1 = __float22bfloat162_rn(make_float2(vr[j].z, vr[j].w));
                uint2 u = make_uint2(*(uint32_t*)&h0, *(uint32_t*)&h1);
                *(uint2*)(d + j * 2 * PIT) = u;
            }
            if (is_c) {
                __nv_bfloat162 h0 = __float22bfloat162_rn(make_float2(vc.x, vc.y));
                __nv_bfloat162 h1 = __float22bfloat162_rn(make_float2(vc.z, vc.w));
                float f0 = __bfloat162float(h0.x), f1 = __bfloat162float(h0.y);
                float f2 = __bfloat162float(h1.x), f3 = __bfloat162float(h1.y);
                csq_loc += f0 * f0 + f1 * f1 + f2 * f2 + f3 * f3;
                uint2 u = make_uint2(*(uint32_t*)&h0, *(uint32_t*)&h1);
                *(uint2*)(pcd + b * BUFE) = u;
            }
        };

        load_tile(0);
        store_tile(0);
        __syncthreads();

        for (int t = 0; t < ntiles; t++) {
            if (t + 1 < ntiles) load_tile(t + 1);

            const uint32_t xb = xbase + (t & 1) * BUFB;
            #pragma unroll
            for (int ks = 0; ks < 4; ks++) {
                const uint32_t ko = xb + (uint32_t)(ks * 32) + lmo;
                uint32_t F0[4], F1[4], F2[4], F3[4], F4[4];
                switch (wid) {
                case 0:   // (0,0) (0,1)
                    ldm_x4(F0, ko); ldm_x4(F1, ko + STRB);
                    mma2(acc[0], F0, F0); mma2(acc[1], F0, F1);
                    break;
                case 1:   // (0,2) (0,3)
                    ldm_x4(F0, ko); ldm_x4(F2, ko + 2 * STRB);
                    ldm_x4(F3, ko + 3 * STRB);
                    mma2(acc[0], F0, F2); mma2(acc[1], F0, F3);
                    break;
                case 2:   // (1,1) (1,2)
                    ldm_x4(F1, ko + STRB); ldm_x4(F2, ko + 2 * STRB);
                    mma2(acc[0], F1, F1); mma2(acc[1], F1, F2);
                    break;
                case 3:   // (1,3) (1,4)
                    ldm_x4(F1, ko + STRB); ldm_x4(F3, ko + 3 * STRB);
                    ldm_x4(F4, ko + 4 * STRB);
                    mma2(acc[0], F1, F3); mma2(acc[1], F1, F4);
                    break;
                case 4:   // (2,2) (2,3)
                    ldm_x4(F2, ko + 2 * STRB); ldm_x4(F3, ko + 3 * STRB);
                    mma2(acc[0], F2, F2); mma2(acc[1], F2, F3);
                    break;
                case 5:   // (2,4) (3,4)
                    ldm_x4(F2, ko + 2 * STRB); ldm_x4(F3, ko + 3 * STRB);
                    ldm_x4(F4, ko + 4 * STRB);
                    mma2(acc[0], F2, F4); mma2(acc[1], F3, F4);
                    break;
                case 6:   // (3,3)
                    ldm_x4(F3, ko + 3 * STRB);
                    mma2(acc[0], F3, F3);
                    break;
                default:  // 7: (0,4)
                    ldm_x4(F0, ko); ldm_x4(F4, ko + 4 * STRB);
                    mma2(acc[0], F0, F4);
                    break;
                }
            }

            if (t + 1 < ntiles) store_tile((t + 1) & 1);
            __syncthreads();
        }

        // centroid ||c||^2: warp 0, lanes 0-15
        if (wid == 0) {
            float v = csq_loc;
            #pragma unroll
            for (int o = 8; o; o >>= 1) v += __shfl_xor_sync(~0u, v, o, 16);
            if (lane == 0) s.csq = v;
        }

        // diag tiles live in slot 0 of warps 0,2,4,6 (strip = wid/2)
        const int R0 = lane >> 2;
        const int Cb = (lane & 3) << 1;
        if ((wid & 1) == 0) {
            #pragma unroll
            for (int h = 0; h < 2; h++)
                #pragma unroll
                for (int q = 0; q < 4; q++) {
                    int rl = R0 + ((q >> 1) << 3);
                    int cl = h * 8 + Cb + (q & 1);
                    if (rl == cl)
                        s.sq_sh[16 * (wid >> 1) + rl] = acc[0][h * 4 + q];
                }
        }
        __syncthreads();

        const float* sq  = s.sq_sh;
        const float  csq = s.csq;
        float rsum = 0.f, asum = 0.f;
        switch (wid) {
        case 0:
            tile_dist<0,0>(acc[0], sq, csq, rsum, asum, R0, Cb);
            tile_dist<0,1>(acc[1], sq, csq, rsum, asum, R0, Cb);
            break;
        case 1:
            tile_dist<0,2>(acc[0], sq, csq, rsum, asum, R0, Cb);
            tile_dist<0,3>(acc[1], sq, csq, rsum, asum, R0, Cb);
            break;
        case 2:
            tile_dist<1,1>(acc[0], sq, csq, rsum, asum, R0, Cb);
            tile_dist<1,2>(acc[1], sq, csq, rsum, asum, R0, Cb);
            break;
        case 3:
            tile_dist<1,3>(acc[0], sq, csq, rsum, asum, R0, Cb);
            tile_dist<1,4>(acc[1], sq, csq, rsum, asum, R0, Cb);
            break;
        case 4:
            tile_dist<2,2>(acc[0], sq, csq, rsum, asum, R0, Cb);
            tile_dist<2,3>(acc[1], sq, csq, rsum, asum, R0, Cb);
            break;
        case 5:
            tile_dist<2,4>(acc[0], sq, csq, rsum, asum, R0, Cb);
            tile_dist<3,4>(acc[1], sq, csq, rsum, asum, R0, Cb);
            break;
        case 6:
            tile_dist<3,3>(acc[0], sq, csq, rsum, asum, R0, Cb);
            break;
        default:
            tile_dist<0,4>(acc[0], sq, csq, rsum, asum, R0, Cb);
            break;
        }

        float part = LAMBDA_1 * inv_align * asum + LAMBDA_2 * inv_rob * rsum;

        #pragma unroll
        for (int o = 16; o; o >>= 1) part += __shfl_xor_sync(~0u, part, o);
        if (lane == 0) s.red[wid] = part;
        __syncthreads();
        if (tid == 0) {
            double acc2 = 0.0;
            #pragma unroll
            for (int i = 0; i < 8; i++) acc2 += (double)s.red[i];
            blk_part = acc2;
        }
    }

    // ================= last-block-done final reduction ====================
    const int nb = (int)gridDim.x;
    if (tid == 0) {
        g_part[blockIdx.x] = blk_part;
        __threadfence();
        int old = atomicAdd(&g_cnt, 1);
        s.done = (old == nb - 1);
    }
    __syncthreads();
    if (s.done) {
        double acc = 0.0;
        for (int i = tid; i < nb; i += 256) acc += __ldcg(&g_part[i]);
        #pragma unroll
        for (int o = 16; o; o >>= 1) acc += __shfl_xor_sync(~0u, acc, o);
        if (lane == 0) s.dred[wid] = acc;
        __syncthreads();
        if (tid < 8) {
            double v = s.dred[tid];
            #pragma unroll
            for (int o = 4; o; o >>= 1) v += __shfl_xor_sync(0xffu, v, o, 8);
            if (tid == 0) { out[0] = (float)v; g_cnt = 0; }
        }
    }
}

// ---------------------------------------------------------------------------
extern "C" void kernel_launch(void* const* d_in, const int* in_sizes, int n_in,
                              void* d_out, int out_size) {
    const float* train = (const float*)d_in[0];
    const int*   tgt   = (const int*)d_in[1];
    const float* unl   = (const float*)d_in[2];
    const int*   cids  = (const int*)d_in[3];
    const int*   mids  = (const int*)d_in[4];

    int n_train = in_sizes[1];
    int C       = in_sizes[0] / n_train;
    int G       = in_sizes[3];
    int K       = in_sizes[4] / G;
    int n_unl   = in_sizes[2] / C;

    float inv_align = 1.0f / (float)n_unl;
    float inv_rob   = 1.0f / ((float)K * (float)n_unl);

    int nCe = (n_train + 7) / 8;
    int nb  = G + nCe;

    fused_kernel<<<nb, 256>>>(train, tgt, unl, cids, mids, (float*)d_out,
                              C, G, n_train, inv_align, inv_rob);
}

// round 12
// speedup vs baseline: 1.5268x; 1.5268x over previous
#include <cuda_runtime.h>
#include <cuda_bf16.h>
#include <cstdint>
#include <cfloat>

// ---------------------------------------------------------------------------
// Loss_46102178955400 — bf16 mma.sync, triangular schedule, coalesced gather,
// deep software pipeline (load issued a full tile-period ahead).
// Group path: 2 groups/CTA, double-buffered smem tiles X[buf][g][80][72] bf16
// (rows 0-63 members, 64 centroid, 65-79 zero).
// ---------------------------------------------------------------------------

#define LAMBDA_1 1.0f
#define LAMBDA_2 0.5f
#define KC     64          // f32 k-chunk per tile (-> 64 bf16 cols)
#define RG     80          // padded rows per group
#define PIT    72          // bf16 row pitch (144 B; conflict-free ldmatrix)
#define PITB   144
#define STRB   (16*PITB)   // bytes per 16-row strip
#define BUFE   (2*RG*PIT)  // bf16 elems per buffer (2 groups)
#define BUFB   (BUFE*2)    // bytes per buffer
#define MAXB   4096

__device__ double g_part[MAXB];
__device__ int    g_cnt = 0;

struct __align__(16) GS {
    __nv_bfloat16 X[2][2][RG][PIT];   // [buf][group][row][col] = 46080 B
    const float*  rowp[130];          // flat row -> gmem row base
    float  sq_sh[128];
    float  csq[2];
    float  red[8];
    double dred[8];
    int    done;
};

__device__ __forceinline__ uint32_t smem_u32(const void* p) {
    uint32_t a;
    asm("{ .reg .u64 t; cvta.to.shared.u64 t, %1; cvt.u32.u64 %0, t; }"
        : "=r"(a) : "l"(p));
    return a;
}
__device__ __forceinline__ void ldm_x4(uint32_t a[4], uint32_t addr) {
    asm volatile("ldmatrix.sync.aligned.m8n8.x4.shared.b16 {%0,%1,%2,%3},[%4];"
                 : "=r"(a[0]), "=r"(a[1]), "=r"(a[2]), "=r"(a[3]) : "r"(addr));
}
__device__ __forceinline__ void mma_bf16(float* c, const uint32_t a[4],
                                         uint32_t b0, uint32_t b1) {
    asm volatile("mma.sync.aligned.m16n8k16.row.col.f32.bf16.bf16.f32 "
                 "{%0,%1,%2,%3},{%4,%5,%6,%7},{%8,%9},{%0,%1,%2,%3};"
                 : "+f"(c[0]), "+f"(c[1]), "+f"(c[2]), "+f"(c[3])
                 : "r"(a[0]), "r"(a[1]), "r"(a[2]), "r"(a[3]), "r"(b0), "r"(b1));
}
__device__ __forceinline__ void mma2(float* c8, const uint32_t A[4],
                                     const uint32_t B[4]) {
    mma_bf16(c8,     A, B[0], B[2]);
    mma_bf16(c8 + 4, A, B[1], B[3]);
}

template<int I, int J>
__device__ __forceinline__ void tile_dist(const float* a8, const float* sq,
                                          float csq, float& rsum, float& asum,
                                          int R0, int Cb) {
    #pragma unroll
    for (int h = 0; h < 2; h++)
        #pragma unroll
        for (int q = 0; q < 4; q++) {
            int r = 16 * I + R0 + ((q >> 1) << 3);
            int c = 16 * J + h * 8 + Cb + (q & 1);
            float v = a8[h * 4 + q];
            if (J < 4) {
                if (c > r) {
                    float d2 = sq[r] + sq[c] - 2.f * v;
                    rsum += (d2 > 0.f) ? sqrtf(d2) : 0.f;
                }
            } else if (c == 64) {
                float d2 = sq[r] + csq - 2.f * v;
                asum += (d2 > 0.f) ? sqrtf(d2) : 0.f;
            }
        }
}

__global__ __launch_bounds__(256, 2)
void fused_kernel(const float* __restrict__ train,
                  const int* __restrict__ tgt,
                  const float* __restrict__ unl,
                  const int* __restrict__ cids,
                  const int* __restrict__ mids,
                  float* __restrict__ out,
                  int C, int G, int n_train,
                  float inv_align, float inv_rob) {
    __shared__ GS s;
    const int tid  = threadIdx.x;
    const int wid  = tid >> 5;
    const int lane = tid & 31;
    const int nGrp = (G + 1) >> 1;

    double blk_part = 0.0;   // valid on tid 0 only

    if ((int)blockIdx.x >= nGrp) {
        // ======================= CE path ==================================
        int row = ((int)blockIdx.x - nGrp) * 8 + wid;
        float nll = 0.f;
        if (row < n_train) {
            const float* x  = train + (size_t)row * C;
            const float4* x4 = (const float4*)x;
            const int nv = C >> 2;
            float4 v[8];
            bool   pv[8];
            #pragma unroll
            for (int q = 0; q < 8; q++) {
                int i = lane + q * 32;
                pv[q] = (i < nv);
                v[q]  = pv[q] ? x4[i] : make_float4(-FLT_MAX, -FLT_MAX,
                                                    -FLT_MAX, -FLT_MAX);
            }
            float mx = -FLT_MAX;
            #pragma unroll
            for (int q = 0; q < 8; q++)
                mx = fmaxf(mx, fmaxf(fmaxf(v[q].x, v[q].y),
                                     fmaxf(v[q].z, v[q].w)));
            for (int c = (nv << 2) + lane; c < C; c += 32) mx = fmaxf(mx, x[c]);
            #pragma unroll
            for (int o = 16; o; o >>= 1)
                mx = fmaxf(mx, __shfl_xor_sync(~0u, mx, o));
            float sm = 0.f;
            #pragma unroll
            for (int q = 0; q < 8; q++) {
                if (pv[q])
                    sm += __expf(v[q].x - mx) + __expf(v[q].y - mx) +
                          __expf(v[q].z - mx) + __expf(v[q].w - mx);
            }
            for (int c = (nv << 2) + lane; c < C; c += 32) sm += __expf(x[c] - mx);
            #pragma unroll
            for (int o = 16; o; o >>= 1) sm += __shfl_xor_sync(~0u, sm, o);
            nll = -(x[tgt[row]] - mx - logf(sm));
        }
        if (lane == 0) s.red[wid] = nll;
        __syncthreads();
        if (tid == 0) {
            double acc = 0.0;
            #pragma unroll
            for (int i = 0; i < 8; i++) acc += (double)s.red[i];
            blk_part = acc / (double)n_train;
        }
    } else {
        // ======================= group path ===============================
        const int g0 = 2 * (int)blockIdx.x;
        int g1 = g0 + 1;
        const float w1 = (g1 < G) ? 1.f : 0.f;
        if (g1 >= G) g1 = g0;

        // flat row -> gmem base pointer table
        if (tid < 128) {
            int gg = (tid < 64) ? g0 : g1;
            s.rowp[tid] = unl + (size_t)mids[gg * 64 + (tid & 63)] * C;
        } else if (tid == 128) {
            s.rowp[128] = train + (size_t)cids[g0] * C;
        } else if (tid == 129) {
            s.rowp[129] = train + (size_t)cids[g1] * C;
        }

        {   // zero pad rows 65..79 in both buffers/groups
            uint32_t* pz = (uint32_t*)&s.X[0][0][0][0];
            for (int i = tid; i < 2 * 2 * 15 * (PIT / 2); i += 256) {
                int bg  = i / (15 * (PIT / 2));
                int rem = i - bg * 15 * (PIT / 2);
                int r   = 65 + rem / (PIT / 2);
                int c   = rem % (PIT / 2);
                pz[(bg * RG + r) * (PIT / 2) + c] = 0u;
            }
        }
        __syncthreads();

        // ---- coalesced load ownership: warp w rows [16w,16w+16) ----------
        const int sub  = lane >> 4;            // 0/1: which of the 2 rows
        const int l16  = lane & 15;            // position within row
        const int cc   = l16 << 2;             // float col within 64-chunk
        const int grp_ld  = wid >> 2;          // group this warp LOADS into
        const int row0_ld = ((wid & 3) << 4) + sub;
        __nv_bfloat16* pdst0 = &s.X[0][grp_ld][row0_ld][cc];
        const bool is_c = (wid < 2) && (lane < 16);
        __nv_bfloat16* pcd = &s.X[0][wid & 1][64][cc];

        float csq_loc = 0.f;

        const int gsel = wid >> 2;
        const int wl   = wid & 3;
        const uint32_t xbase_g = smem_u32(&s.X[0][gsel][0][0]);
        const int q8 = lane >> 3;
        const uint32_t lmo = (uint32_t)(((lane & 7) + ((q8 & 1) << 3)) * PITB +
                                        (((q8 >> 1) << 3) << 1));

        float acc[4][8];
        #pragma unroll
        for (int i = 0; i < 4; i++)
            #pragma unroll
            for (int j = 0; j < 8; j++) acc[i][j] = 0.f;

        const int ntiles = (C + KC - 1) / KC;
        float4 vr[8], vc = make_float4(0.f, 0.f, 0.f, 0.f);

        auto load_tile = [&](int t) {
            const int c0 = t * KC, cols = C - c0;
            const int fl0 = (wid << 4) + sub;        // flat row for j=0
            if (cols >= KC) {
                #pragma unroll
                for (int j = 0; j < 8; j++) {
                    const float* p = s.rowp[fl0 + 2 * j];
                    vr[j] = *(const float4*)(p + c0 + cc);
                }
                if (is_c) {
                    const float* p = s.rowp[128 + (wid & 1)];
                    vc = *(const float4*)(p + c0 + cc);
                }
            } else {
                const bool full = (cc + 4 <= cols);
                #pragma unroll
                for (int j = 0; j < 8; j++) {
                    const float* p = s.rowp[fl0 + 2 * j] + c0 + cc;
                    float4 v = make_float4(0.f, 0.f, 0.f, 0.f);
                    if (full) v = *(const float4*)p;
                    else {
                        if (cc + 0 < cols) v.x = p[0];
                        if (cc + 1 < cols) v.y = p[1];
                        if (cc + 2 < cols) v.z = p[2];
                    }
                    vr[j] = v;
                }
                if (is_c) {
                    const float* p = s.rowp[128 + (wid & 1)] + c0 + cc;
                    float4 v = make_float4(0.f, 0.f, 0.f, 0.f);
                    if (full) v = *(const float4*)p;
                    else {
                        if (cc + 0 < cols) v.x = p[0];
                        if (cc + 1 < cols) v.y = p[1];
                        if (cc + 2 < cols) v.z = p[2];
                    }
                    vc = v;
                }
            }
        };
        auto store_tile = [&](int b) {
            __nv_bfloat16* d = pdst0 + b * BUFE;
            #pragma unroll
            for (int j = 0; j < 8; j++) {
                __nv_bfloat162 h0 = __float22bfloat162_rn(make_float2(vr[j].x, vr[j].y));
                __nv_bfloat162 h1 = __float22bfloat162_rn(make_float2(vr[j].z, vr[j].w));
                uint2 u = make_uint2(*(uint32_t*)&h0, *(uint32_t*)&h1);
                *(uint2*)(d + j * 2 * PIT) = u;      // +2 rows per j
            }
            if (is_c) {
                __nv_bfloat162 h0 = __float22bfloat162_rn(make_float2(vc.x, vc.y));
                __nv_bfloat162 h1 = __float22bfloat162_rn(make_float2(vc.z, vc.w));
                float f0 = __bfloat162float(h0.x), f1 = __bfloat162float(h0.y);
                float f2 = __bfloat162float(h1.x), f3 = __bfloat162float(h1.y);
                csq_loc += f0 * f0 + f1 * f1 + f2 * f2 + f3 * f3;
                uint2 u = make_uint2(*(uint32_t*)&h0, *(uint32_t*)&h1);
                *(uint2*)(pcd + b * BUFE) = u;
            }
        };

        // deep pipeline prologue: tile0 stored, tile1 in registers/in flight
        load_tile(0);
        store_tile(0);
        if (ntiles > 1) load_tile(1);
        __syncthreads();

        for (int t = 0; t < ntiles; t++) {
            // store tile t+1 (loaded a full tile-period ago), then issue
            // loads for tile t+2; MMA(t) hides both.
            if (t + 1 < ntiles) store_tile((t + 1) & 1);
            if (t + 2 < ntiles) load_tile(t + 2);

            const uint32_t xb = xbase_g + (t & 1) * BUFB;
            #pragma unroll
            for (int ks = 0; ks < 4; ks++) {
                const uint32_t ko = xb + (uint32_t)(ks * 32) + lmo;
                uint32_t F0[4], F1[4], F2[4], F3[4], F4[4];
                if (wl == 0) {
                    ldm_x4(F0, ko);            ldm_x4(F1, ko + STRB);
                    ldm_x4(F2, ko + 2 * STRB); ldm_x4(F3, ko + 3 * STRB);
                    mma2(acc[0], F0, F0); mma2(acc[1], F0, F1);
                    mma2(acc[2], F0, F2); mma2(acc[3], F0, F3);
                } else if (wl == 1) {
                    ldm_x4(F0, ko);            ldm_x4(F1, ko + STRB);
                    ldm_x4(F2, ko + 2 * STRB); ldm_x4(F3, ko + 3 * STRB);
                    ldm_x4(F4, ko + 4 * STRB);
                    mma2(acc[0], F1, F1); mma2(acc[1], F1, F2);
                    mma2(acc[2], F1, F3); mma2(acc[3], F0, F4);
                } else if (wl == 2) {
                    ldm_x4(F1, ko + STRB);     ldm_x4(F2, ko + 2 * STRB);
                    ldm_x4(F3, ko + 3 * STRB); ldm_x4(F4, ko + 4 * STRB);
                    mma2(acc[0], F2, F2); mma2(acc[1], F2, F3);
                    mma2(acc[2], F1, F4); mma2(acc[3], F2, F4);
                } else {
                    ldm_x4(F3, ko + 3 * STRB); ldm_x4(F4, ko + 4 * STRB);
                    mma2(acc[0], F3, F3); mma2(acc[1], F3, F4);
                }
            }
            __syncthreads();
        }

        // centroid ||c||^2: warps 0/1, lanes 0-15 hold partials
        if (wid < 2) {
            float v = csq_loc;
            #pragma unroll
            for (int o = 8; o; o >>= 1) v += __shfl_xor_sync(~0u, v, o, 16);
            if (lane == 0) s.csq[wid] = v;
        }

        const int R0 = lane >> 2;
        const int Cb = (lane & 3) << 1;
        #pragma unroll
        for (int h = 0; h < 2; h++)
            #pragma unroll
            for (int q = 0; q < 4; q++) {
                int rl = R0 + ((q >> 1) << 3);
                int cl = h * 8 + Cb + (q & 1);
                if (rl == cl)
                    s.sq_sh[(gsel << 6) + 16 * wl + rl] = acc[0][h * 4 + q];
            }
        __syncthreads();

        const float* sq  = &s.sq_sh[gsel << 6];
        const float  csq = s.csq[gsel];
        float rsum = 0.f, asum = 0.f;
        if (wl == 0) {
            tile_dist<0,0>(acc[0], sq, csq, rsum, asum, R0, Cb);
            tile_dist<0,1>(acc[1], sq, csq, rsum, asum, R0, Cb);
            tile_dist<0,2>(acc[2], sq, csq, rsum, asum, R0, Cb);
            tile_dist<0,3>(acc[3], sq, csq, rsum, asum, R0, Cb);
        } else if (wl == 1) {
            tile_dist<1,1>(acc[0], sq, csq, rsum, asum, R0, Cb);
            tile_dist<1,2>(acc[1], sq, csq, rsum, asum, R0, Cb);
            tile_dist<1,3>(acc[2], sq, csq, rsum, asum, R0, Cb);
            tile_dist<0,4>(acc[3], sq, csq, rsum, asum, R0, Cb);
        } else if (wl == 2) {
            tile_dist<2,2>(acc[0], sq, csq, rsum, asum, R0, Cb);
            tile_dist<2,3>(acc[1], sq, csq, rsum, asum, R0, Cb);
            tile_dist<1,4>(acc[2], sq, csq, rsum, asum, R0, Cb);
            tile_dist<2,4>(acc[3], sq, csq, rsum, asum, R0, Cb);
        } else {
            tile_dist<3,3>(acc[0], sq, csq, rsum, asum, R0, Cb);
            tile_dist<3,4>(acc[1], sq, csq, rsum, asum, R0, Cb);
        }

        float w = gsel ? w1 : 1.f;
        float part = w * (LAMBDA_1 * inv_align * asum + LAMBDA_2 * inv_rob * rsum);

        #pragma unroll
        for (int o = 16; o; o >>= 1) part += __shfl_xor_sync(~0u, part, o);
        if (lane == 0) s.red[wid] = part;
        __syncthreads();
        if (tid == 0) {
            double acc2 = 0.0;
            #pragma unroll
            for (int i = 0; i < 8; i++) acc2 += (double)s.red[i];
            blk_part = acc2;
        }
    }

    // ================= last-block-done final reduction ====================
    const int nb = (int)gridDim.x;
    if (tid == 0) {
        g_part[blockIdx.x] = blk_part;
        __threadfence();
        int old = atomicAdd(&g_cnt, 1);
        s.done = (old == nb - 1);
    }
    __syncthreads();
    if (s.done) {
        double acc = 0.0;
        for (int i = tid; i < nb; i += 256) acc += __ldcg(&g_part[i]);
        #pragma unroll
        for (int o = 16; o; o >>= 1) acc += __shfl_xor_sync(~0u, acc, o);
        if (lane == 0) s.dred[wid] = acc;
        __syncthreads();
        if (tid < 8) {
            double v = s.dred[tid];
            #pragma unroll
            for (int o = 4; o; o >>= 1) v += __shfl_xor_sync(0xffu, v, o, 8);
            if (tid == 0) { out[0] = (float)v; g_cnt = 0; }
        }
    }
}

// ---------------------------------------------------------------------------
extern "C" void kernel_launch(void* const* d_in, const int* in_sizes, int n_in,
                              void* d_out, int out_size) {
    const float* train = (const float*)d_in[0];
    const int*   tgt   = (const int*)d_in[1];
    const float* unl   = (const float*)d_in[2];
    const int*   cids  = (const int*)d_in[3];
    const int*   mids  = (const int*)d_in[4];

    int n_train = in_sizes[1];
    int C       = in_sizes[0] / n_train;
    int G       = in_sizes[3];
    int K       = in_sizes[4] / G;
    int n_unl   = in_sizes[2] / C;

    float inv_align = 1.0f / (float)n_unl;
    float inv_rob   = 1.0f / ((float)K * (float)n_unl);

    int nGrp = (G + 1) / 2;
    int nCe  = (n_train + 7) / 8;
    int nb   = nGrp + nCe;

    fused_kernel<<<nb, 256>>>(train, tgt, unl, cids, mids, (float*)d_out,
                              C, G, n_train, inv_align, inv_rob);
}